// round 14
// baseline (speedup 1.0000x reference)
#include <cuda_runtime.h>

#define RES 300
#define NCH 64            // NC_A + NC_D
#define NC_A 48
#define APP_DIM 27
#define SPB 128           // samples per block
#define BLOCK 128

typedef unsigned long long u64;

__device__ __forceinline__ u64 fma2(u64 a, u64 b, u64 c) {
    u64 d; asm("fma.rn.f32x2 %0, %1, %2, %3;" : "=l"(d) : "l"(a), "l"(b), "l"(c));
    return d;
}
__device__ __forceinline__ u64 mul2(u64 a, u64 b) {
    u64 d; asm("mul.rn.f32x2 %0, %1, %2;" : "=l"(d) : "l"(a), "l"(b));
    return d;
}
__device__ __forceinline__ u64 add2(u64 a, u64 b) {
    u64 d; asm("add.rn.f32x2 %0, %1, %2;" : "=l"(d) : "l"(a), "l"(b));
    return d;
}
__device__ __forceinline__ u64 pack2(float x) {
    u64 d; asm("mov.b64 %0, {%1, %1};" : "=l"(d) : "f"(x));
    return d;
}
__device__ __forceinline__ float lo32(u64 v) {
    return __uint_as_float((unsigned)(v & 0xffffffffULL));
}
__device__ __forceinline__ float hi32(u64 v) {
    return __uint_as_float((unsigned)(v >> 32));
}

// Scratch (zero-initialized device globals; pads never written -> stay 0)
__device__ float g_plane_t[3 * RES * RES * NCH + 64];  // (i, h, w, c) + pad
__device__ float g_line_t[3 * RES * NCH + 64];         // (i, h, c)    + pad

// ---------------------------------------------------------------------------
// Merged transpose: plane (3,64,300,300)->(3,300,300,64), line -> (3,300,64)
// ---------------------------------------------------------------------------
__global__ void transpose_kernel(const float* __restrict__ plane,
                                 const float* __restrict__ line) {
    int ih = blockIdx.x;            // 0..899
    int i = ih / RES, h = ih % RES;

    if (blockIdx.y == 10) {
        if (threadIdx.x < NCH)
            g_line_t[((size_t)i * RES + h) * NCH + threadIdx.x] =
                line[((size_t)i * NCH + threadIdx.x) * RES + h];
        return;
    }

    int w0 = blockIdx.y * 30;
    __shared__ float tile[NCH][31];

    for (int idx = threadIdx.x; idx < NCH * 30; idx += blockDim.x) {
        int c = idx / 30, w = idx % 30;
        tile[c][w] = plane[(((size_t)i * NCH + c) * RES + h) * RES + w0 + w];
    }
    __syncthreads();
    float* dst = g_plane_t + (((size_t)i * RES + h) * RES + w0) * NCH;
    for (int idx = threadIdx.x; idx < NCH * 30; idx += blockDim.x) {
        int w = idx / NCH, c = idx % NCH;
        dst[(size_t)w * NCH + c] = tile[c][w];
    }
}

// ---------------------------------------------------------------------------
// Fused kernel, WARP-AUTONOMOUS mode pipeline (no block barriers after init):
//   each warp owns 32 samples + a private F slab (32 x 68 floats)
//   for i in 0..2:  gather_i -> syncwarp -> project_i -> syncwarp
// smem (floats): xyz[384] | W[144][28] | slabs[4][32*68]  (52.5 KB, 4 blk/SM)
// ---------------------------------------------------------------------------
#define XYZ_OFF 0
#define W_OFF   (3 * SPB)                       // 384
#define F_OFF   (W_OFF + 144 * 28)              // 4416
#define SLAB    (32 * 68)                       // floats per warp slab
#define F_ROW2  17                              // 68 floats = 17 x 16B
#define SMEM_FLOATS (F_OFF + 4 * SLAB)          // 13120 -> 52480 bytes

__global__ void __launch_bounds__(BLOCK, 4)
fused_kernel(const float* __restrict__ xyz,
             const float* __restrict__ basisW,   // (27, 144) row-major
             float* __restrict__ out, int N)
{
    extern __shared__ __align__(16) float sm[];
    float* xyzsm = sm + XYZ_OFF;
    float* Wsm   = sm + W_OFF;

    const int tid = threadIdx.x;
    const long base = (long)blockIdx.x * SPB;

    // ---- phase 0: stage xyz + W (broadcast layout, zero pad col) ----
    for (int idx = tid; idx < 3 * SPB; idx += BLOCK) {
        long g = base * 3 + idx;
        xyzsm[idx] = (g < (long)3 * N) ? xyz[g] : 0.f;
    }
    for (int idx = tid; idx < APP_DIM * 144; idx += BLOCK) {
        int d = idx / 144, j = idx - d * 144;
        Wsm[j * 28 + d] = basisW[idx];           // coalesced global read
    }
    if (tid < 144) Wsm[tid * 28 + 27] = 0.f;
    __syncthreads();                              // the ONLY block barrier

    const ulonglong2* GP = (const ulonglong2*)g_plane_t;
    const ulonglong2* GL = (const ulonglong2*)g_line_t;
    const int lane = tid & 31;
    const int c4   = lane & 15;         // channel quad within 16-lane group
    const int half = lane >> 4;         // which sample of the pair
    const int wrp  = tid >> 5;          // 0..3

    ulonglong2* F2 = (ulonglong2*)(sm + F_OFF + wrp * SLAB);  // warp slab
    const float* xyzw = xyzsm + wrp * 32 * 3;                 // warp's xyz

    u64 acc2[14];
#pragma unroll
    for (int k = 0; k < 14; k++) acc2[k] = 0ULL;
    u64 sig2 = 0ULL;

#pragma unroll
    for (int i = 0; i < 3; i++) {
        // ---- gather_i: 16-lane group per sample, into warp slab ----
#pragma unroll 2
        for (int k = 0; k < 16; k++) {
            int sl = k * 2 + half;               // slab row 0..31
            float cx = xyzw[sl * 3 + 0];
            float cy = xyzw[sl * 3 + 1];
            float cz = xyzw[sl * 3 + 2];
            // MAT_MODE = {0,1},{0,2},{1,2}; VEC_MODE = {2,1,0}
            float gx = (i == 2) ? cy : cx;
            float gy = (i == 0) ? cy : cz;
            float gz = (i == 0) ? cz : ((i == 1) ? cy : cx);

            float ix = (gx + 1.f) * 0.5f * (float)(RES - 1);
            float iy = (gy + 1.f) * 0.5f * (float)(RES - 1);
            float iz = (gz + 1.f) * 0.5f * (float)(RES - 1);
            float x0f = floorf(ix), y0f = floorf(iy), z0f = floorf(iz);
            int x0 = (int)x0f, y0 = (int)y0f, z0 = (int)z0f;
            float wx = ix - x0f, wy = iy - y0f, wz = iz - z0f;
            int y1 = y0 + 1;
            if (y1 > RES - 1) { y1 = RES - 1; wy = 0.f; }
            // x/z +1 may read one quad past the row (pad): weight 0
            if (x0 + 1 > RES - 1) wx = 0.f;
            if (z0 + 1 > RES - 1) wz = 0.f;

            int r0 = (i * RES + y0) * RES + x0;
            int r1 = (i * RES + y1) * RES + x0;
            int rl =  i * RES + z0;
            ulonglong2 a00 = GP[r0 * 16 + c4];
            ulonglong2 a01 = GP[(r0 + 1) * 16 + c4];
            ulonglong2 a10 = GP[r1 * 16 + c4];
            ulonglong2 a11 = GP[(r1 + 1) * 16 + c4];
            ulonglong2 l0  = GL[rl * 16 + c4];
            ulonglong2 l1  = GL[(rl + 1) * 16 + c4];

            u64 w00p = pack2((1.f - wx) * (1.f - wy));
            u64 w01p = pack2(wx * (1.f - wy));
            u64 w10p = pack2((1.f - wx) * wy);
            u64 w11p = pack2(wx * wy);
            u64 wl0p = pack2(1.f - wz);
            u64 wl1p = pack2(wz);

            ulonglong2 f;
            u64 t, u;
            t = fma2(w00p, a00.x, fma2(w01p, a01.x,
                 fma2(w10p, a10.x, mul2(w11p, a11.x))));
            u = fma2(wl0p, l0.x, mul2(wl1p, l1.x));
            f.x = mul2(t, u);
            t = fma2(w00p, a00.y, fma2(w01p, a01.y,
                 fma2(w10p, a10.y, mul2(w11p, a11.y))));
            u = fma2(wl0p, l0.y, mul2(wl1p, l1.y));
            f.y = mul2(t, u);

            F2[sl * F_ROW2 + c4] = f;
        }
        __syncwarp();

        // ---- project_i: thread-per-sample from warp slab, W broadcast ----
        {
            const int fb = lane * F_ROW2;
            const float* wb = Wsm + i * NC_A * 28;

#pragma unroll 2
            for (int c4i = 0; c4i < NC_A / 4; c4i++) {
                float4 f = ((const float4*)F2)[fb + c4i];
                u64 fx = pack2(f.x), fy = pack2(f.y);
                u64 fz = pack2(f.z), fw = pack2(f.w);
                const ulonglong2* q0 = (const ulonglong2*)(wb + c4i * 4 * 28);
                const ulonglong2* q1 = (const ulonglong2*)(wb + c4i * 4 * 28 + 28);
                const ulonglong2* q2 = (const ulonglong2*)(wb + c4i * 4 * 28 + 56);
                const ulonglong2* q3 = (const ulonglong2*)(wb + c4i * 4 * 28 + 84);
#pragma unroll
                for (int p = 0; p < 7; p++) {
                    ulonglong2 v0 = q0[p], v1 = q1[p], v2 = q2[p], v3 = q3[p];
                    acc2[2*p]   = fma2(fx, v0.x, acc2[2*p]);
                    acc2[2*p+1] = fma2(fx, v0.y, acc2[2*p+1]);
                    acc2[2*p]   = fma2(fy, v1.x, acc2[2*p]);
                    acc2[2*p+1] = fma2(fy, v1.y, acc2[2*p+1]);
                    acc2[2*p]   = fma2(fz, v2.x, acc2[2*p]);
                    acc2[2*p+1] = fma2(fz, v2.y, acc2[2*p+1]);
                    acc2[2*p]   = fma2(fw, v3.x, acc2[2*p]);
                    acc2[2*p+1] = fma2(fw, v3.y, acc2[2*p+1]);
                }
            }
#pragma unroll
            for (int c4i = NC_A / 4; c4i < NCH / 4; c4i++) {
                ulonglong2 fd = F2[fb + c4i];
                sig2 = add2(sig2, add2(fd.x, fd.y));
            }
        }
        if (i < 2) __syncwarp();        // slab reused next mode
    }

    // ---- write out ----
    long n = base + wrp * 32 + lane;
    if (n < N) {
        out[n] = lo32(sig2) + hi32(sig2);
        float* ao = out + N + n * APP_DIM;
#pragma unroll
        for (int p = 0; p < 13; p++) {
            ao[2*p]   = lo32(acc2[p]);
            ao[2*p+1] = hi32(acc2[p]);
        }
        ao[26] = lo32(acc2[13]);
    }
}

extern "C" void kernel_launch(void* const* d_in, const int* in_sizes, int n_in,
                              void* d_out, int out_size) {
    const float* xyz   = (const float*)d_in[0];   // (N, 3)
    const float* plane = (const float*)d_in[1];   // (3, 64, 300, 300)
    const float* line  = (const float*)d_in[2];   // (3, 64, 300, 1)
    const float* W     = (const float*)d_in[3];   // (27, 144)
    float* out = (float*)d_out;
    int N = in_sizes[0] / 3;

    transpose_kernel<<<dim3(3 * RES, 11), 256>>>(plane, line);

    int smem_bytes = SMEM_FLOATS * (int)sizeof(float);   // 52480
    cudaFuncSetAttribute(fused_kernel,
                         cudaFuncAttributeMaxDynamicSharedMemorySize, smem_bytes);
    int grid = (N + SPB - 1) / SPB;
    fused_kernel<<<grid, BLOCK, smem_bytes>>>(xyz, W, out, N);
}

// round 15
// speedup vs baseline: 1.4348x; 1.4348x over previous
#include <cuda_runtime.h>

#define RES 300
#define NCH 64            // NC_A + NC_D
#define NC_A 48
#define APP_DIM 27
#define SPB 128           // samples per block
#define BLOCK 128

typedef unsigned long long u64;

__device__ __forceinline__ u64 fma2(u64 a, u64 b, u64 c) {
    u64 d; asm("fma.rn.f32x2 %0, %1, %2, %3;" : "=l"(d) : "l"(a), "l"(b), "l"(c));
    return d;
}
__device__ __forceinline__ u64 mul2(u64 a, u64 b) {
    u64 d; asm("mul.rn.f32x2 %0, %1, %2;" : "=l"(d) : "l"(a), "l"(b));
    return d;
}
__device__ __forceinline__ u64 add2(u64 a, u64 b) {
    u64 d; asm("add.rn.f32x2 %0, %1, %2;" : "=l"(d) : "l"(a), "l"(b));
    return d;
}
__device__ __forceinline__ u64 pack2(float x) {
    u64 d; asm("mov.b64 %0, {%1, %1};" : "=l"(d) : "f"(x));
    return d;
}
__device__ __forceinline__ float lo32(u64 v) {
    return __uint_as_float((unsigned)(v & 0xffffffffULL));
}
__device__ __forceinline__ float hi32(u64 v) {
    return __uint_as_float((unsigned)(v >> 32));
}

// Scratch (zero-initialized device globals; pads never written -> stay 0)
__device__ float g_plane_t[3 * RES * RES * NCH + 64];  // (i, h, w, c) + pad
__device__ float g_line_t[3 * RES * NCH + 64];         // (i, h, c)    + pad

// ---------------------------------------------------------------------------
// Merged transpose: plane (3,64,300,300)->(3,300,300,64), line -> (3,300,64)
// ---------------------------------------------------------------------------
__global__ void transpose_kernel(const float* __restrict__ plane,
                                 const float* __restrict__ line) {
    int ih = blockIdx.x;            // 0..899
    int i = ih / RES, h = ih % RES;

    if (blockIdx.y == 10) {
        if (threadIdx.x < NCH)
            g_line_t[((size_t)i * RES + h) * NCH + threadIdx.x] =
                line[((size_t)i * NCH + threadIdx.x) * RES + h];
        return;
    }

    int w0 = blockIdx.y * 30;
    __shared__ float tile[NCH][31];

    for (int idx = threadIdx.x; idx < NCH * 30; idx += blockDim.x) {
        int c = idx / 30, w = idx % 30;
        tile[c][w] = plane[(((size_t)i * NCH + c) * RES + h) * RES + w0 + w];
    }
    __syncthreads();
    float* dst = g_plane_t + (((size_t)i * RES + h) * RES + w0) * NCH;
    for (int idx = threadIdx.x; idx < NCH * 30; idx += blockDim.x) {
        int w = idx / NCH, c = idx % NCH;
        dst[(size_t)w * NCH + c] = tile[c][w];
    }
}

// ---------------------------------------------------------------------------
// Fused kernel, WARP-AUTONOMOUS mode pipeline (no block barriers after init):
//   each warp owns 32 samples + a private F slab (32 x 68 floats)
//   for i in 0..2:  gather_i -> syncwarp -> project_i -> syncwarp
// smem (floats): xyz[384] | W[144][28] | slabs[4][32*68]  (52.5 KB, 4 blk/SM)
// ---------------------------------------------------------------------------
#define XYZ_OFF 0
#define W_OFF   (3 * SPB)                       // 384
#define F_OFF   (W_OFF + 144 * 28)              // 4416
#define SLAB    (32 * 68)                       // floats per warp slab
#define F_ROW2  17                              // 68 floats = 17 x 16B
#define SMEM_FLOATS (F_OFF + 4 * SLAB)          // 13120 -> 52480 bytes

__global__ void __launch_bounds__(BLOCK, 4)
fused_kernel(const float* __restrict__ xyz,
             const float* __restrict__ basisW,   // (27, 144) row-major
             float* __restrict__ out, int N)
{
    extern __shared__ __align__(16) float sm[];
    float* xyzsm = sm + XYZ_OFF;
    float* Wsm   = sm + W_OFF;

    const int tid = threadIdx.x;
    const long base = (long)blockIdx.x * SPB;

    // ---- phase 0: stage xyz + W (broadcast layout, zero pad col) ----
    for (int idx = tid; idx < 3 * SPB; idx += BLOCK) {
        long g = base * 3 + idx;
        xyzsm[idx] = (g < (long)3 * N) ? xyz[g] : 0.f;
    }
    for (int idx = tid; idx < APP_DIM * 144; idx += BLOCK) {
        int d = idx / 144, j = idx - d * 144;
        Wsm[j * 28 + d] = basisW[idx];           // coalesced global read
    }
    if (tid < 144) Wsm[tid * 28 + 27] = 0.f;
    __syncthreads();                              // the ONLY block barrier

    const ulonglong2* GP = (const ulonglong2*)g_plane_t;
    const ulonglong2* GL = (const ulonglong2*)g_line_t;
    const int lane = tid & 31;
    const int c4   = lane & 15;         // channel quad within 16-lane group
    const int half = lane >> 4;         // which sample of the pair
    const int wrp  = tid >> 5;          // 0..3

    ulonglong2* F2 = (ulonglong2*)(sm + F_OFF + wrp * SLAB);  // warp slab
    const float* xyzw = xyzsm + wrp * 32 * 3;                 // warp's xyz

    u64 acc2[14];
#pragma unroll
    for (int k = 0; k < 14; k++) acc2[k] = 0ULL;
    u64 sig2 = 0ULL;

#pragma unroll
    for (int i = 0; i < 3; i++) {
        // ---- gather_i: 16-lane group per sample, into warp slab ----
#pragma unroll 2
        for (int k = 0; k < 16; k++) {
            int sl = k * 2 + half;               // slab row 0..31
            float cx = xyzw[sl * 3 + 0];
            float cy = xyzw[sl * 3 + 1];
            float cz = xyzw[sl * 3 + 2];
            // MAT_MODE = {0,1},{0,2},{1,2}; VEC_MODE = {2,1,0}
            float gx = (i == 2) ? cy : cx;
            float gy = (i == 0) ? cy : cz;
            float gz = (i == 0) ? cz : ((i == 1) ? cy : cx);

            float ix = (gx + 1.f) * 0.5f * (float)(RES - 1);
            float iy = (gy + 1.f) * 0.5f * (float)(RES - 1);
            float iz = (gz + 1.f) * 0.5f * (float)(RES - 1);
            float x0f = floorf(ix), y0f = floorf(iy), z0f = floorf(iz);
            int x0 = (int)x0f, y0 = (int)y0f, z0 = (int)z0f;
            float wx = ix - x0f, wy = iy - y0f, wz = iz - z0f;
            int y1 = y0 + 1;
            if (y1 > RES - 1) { y1 = RES - 1; wy = 0.f; }
            // x/z +1 may read one quad past the row (pad): weight 0
            if (x0 + 1 > RES - 1) wx = 0.f;
            if (z0 + 1 > RES - 1) wz = 0.f;

            int r0 = (i * RES + y0) * RES + x0;
            int r1 = (i * RES + y1) * RES + x0;
            int rl =  i * RES + z0;
            ulonglong2 a00 = GP[r0 * 16 + c4];
            ulonglong2 a01 = GP[(r0 + 1) * 16 + c4];
            ulonglong2 a10 = GP[r1 * 16 + c4];
            ulonglong2 a11 = GP[(r1 + 1) * 16 + c4];
            ulonglong2 l0  = GL[rl * 16 + c4];
            ulonglong2 l1  = GL[(rl + 1) * 16 + c4];

            u64 w00p = pack2((1.f - wx) * (1.f - wy));
            u64 w01p = pack2(wx * (1.f - wy));
            u64 w10p = pack2((1.f - wx) * wy);
            u64 w11p = pack2(wx * wy);
            u64 wl0p = pack2(1.f - wz);
            u64 wl1p = pack2(wz);

            ulonglong2 f;
            u64 t, u;
            t = fma2(w00p, a00.x, fma2(w01p, a01.x,
                 fma2(w10p, a10.x, mul2(w11p, a11.x))));
            u = fma2(wl0p, l0.x, mul2(wl1p, l1.x));
            f.x = mul2(t, u);
            t = fma2(w00p, a00.y, fma2(w01p, a01.y,
                 fma2(w10p, a10.y, mul2(w11p, a11.y))));
            u = fma2(wl0p, l0.y, mul2(wl1p, l1.y));
            f.y = mul2(t, u);

            F2[sl * F_ROW2 + c4] = f;
        }
        __syncwarp();

        // ---- project_i: thread-per-sample from warp slab, W broadcast ----
        {
            const int fb = lane * F_ROW2;
            const float* wb = Wsm + i * NC_A * 28;

#pragma unroll 2
            for (int c4i = 0; c4i < NC_A / 4; c4i++) {
                float4 f = ((const float4*)F2)[fb + c4i];
                u64 fx = pack2(f.x), fy = pack2(f.y);
                u64 fz = pack2(f.z), fw = pack2(f.w);
                const ulonglong2* q0 = (const ulonglong2*)(wb + c4i * 4 * 28);
                const ulonglong2* q1 = (const ulonglong2*)(wb + c4i * 4 * 28 + 28);
                const ulonglong2* q2 = (const ulonglong2*)(wb + c4i * 4 * 28 + 56);
                const ulonglong2* q3 = (const ulonglong2*)(wb + c4i * 4 * 28 + 84);
#pragma unroll
                for (int p = 0; p < 7; p++) {
                    ulonglong2 v0 = q0[p], v1 = q1[p], v2 = q2[p], v3 = q3[p];
                    acc2[2*p]   = fma2(fx, v0.x, acc2[2*p]);
                    acc2[2*p+1] = fma2(fx, v0.y, acc2[2*p+1]);
                    acc2[2*p]   = fma2(fy, v1.x, acc2[2*p]);
                    acc2[2*p+1] = fma2(fy, v1.y, acc2[2*p+1]);
                    acc2[2*p]   = fma2(fz, v2.x, acc2[2*p]);
                    acc2[2*p+1] = fma2(fz, v2.y, acc2[2*p+1]);
                    acc2[2*p]   = fma2(fw, v3.x, acc2[2*p]);
                    acc2[2*p+1] = fma2(fw, v3.y, acc2[2*p+1]);
                }
            }
#pragma unroll
            for (int c4i = NC_A / 4; c4i < NCH / 4; c4i++) {
                ulonglong2 fd = F2[fb + c4i];
                sig2 = add2(sig2, add2(fd.x, fd.y));
            }
        }
        if (i < 2) __syncwarp();        // slab reused next mode
    }

    // ---- write out ----
    long n = base + wrp * 32 + lane;
    if (n < N) {
        out[n] = lo32(sig2) + hi32(sig2);
        float* ao = out + N + n * APP_DIM;
#pragma unroll
        for (int p = 0; p < 13; p++) {
            ao[2*p]   = lo32(acc2[p]);
            ao[2*p+1] = hi32(acc2[p]);
        }
        ao[26] = lo32(acc2[13]);
    }
}

extern "C" void kernel_launch(void* const* d_in, const int* in_sizes, int n_in,
                              void* d_out, int out_size) {
    const float* xyz   = (const float*)d_in[0];   // (N, 3)
    const float* plane = (const float*)d_in[1];   // (3, 64, 300, 300)
    const float* line  = (const float*)d_in[2];   // (3, 64, 300, 1)
    const float* W     = (const float*)d_in[3];   // (27, 144)
    float* out = (float*)d_out;
    int N = in_sizes[0] / 3;

    transpose_kernel<<<dim3(3 * RES, 11), 256>>>(plane, line);

    int smem_bytes = SMEM_FLOATS * (int)sizeof(float);   // 52480
    cudaFuncSetAttribute(fused_kernel,
                         cudaFuncAttributeMaxDynamicSharedMemorySize, smem_bytes);
    int grid = (N + SPB - 1) / SPB;
    fused_kernel<<<grid, BLOCK, smem_bytes>>>(xyz, W, out, N);
}

// round 16
// speedup vs baseline: 1.4374x; 1.0018x over previous
#include <cuda_runtime.h>

#define RES 300
#define NCH 64            // NC_A + NC_D
#define NC_A 48
#define APP_DIM 27
#define SPB 128           // samples per block
#define BLOCK 128

typedef unsigned long long u64;

__device__ __forceinline__ u64 fma2(u64 a, u64 b, u64 c) {
    u64 d; asm("fma.rn.f32x2 %0, %1, %2, %3;" : "=l"(d) : "l"(a), "l"(b), "l"(c));
    return d;
}
__device__ __forceinline__ u64 mul2(u64 a, u64 b) {
    u64 d; asm("mul.rn.f32x2 %0, %1, %2;" : "=l"(d) : "l"(a), "l"(b));
    return d;
}
__device__ __forceinline__ u64 add2(u64 a, u64 b) {
    u64 d; asm("add.rn.f32x2 %0, %1, %2;" : "=l"(d) : "l"(a), "l"(b));
    return d;
}
__device__ __forceinline__ u64 pack2(float x) {
    u64 d; asm("mov.b64 %0, {%1, %1};" : "=l"(d) : "f"(x));
    return d;
}
__device__ __forceinline__ float lo32(u64 v) {
    return __uint_as_float((unsigned)(v & 0xffffffffULL));
}
__device__ __forceinline__ float hi32(u64 v) {
    return __uint_as_float((unsigned)(v >> 32));
}

// Scratch (zero-initialized device globals; pads never written -> stay 0)
__device__ float g_plane_t[3 * RES * RES * NCH + 64];  // (i, h, w, c) + pad
__device__ float g_line_t[3 * RES * NCH + 64];         // (i, h, c)    + pad

// ---------------------------------------------------------------------------
// Merged transpose: plane (3,64,300,300)->(3,300,300,64), line -> (3,300,64)
// ---------------------------------------------------------------------------
__global__ void transpose_kernel(const float* __restrict__ plane,
                                 const float* __restrict__ line) {
    int ih = blockIdx.x;            // 0..899
    int i = ih / RES, h = ih % RES;

    if (blockIdx.y == 10) {
        if (threadIdx.x < NCH)
            g_line_t[((size_t)i * RES + h) * NCH + threadIdx.x] =
                line[((size_t)i * NCH + threadIdx.x) * RES + h];
        return;
    }

    int w0 = blockIdx.y * 30;
    __shared__ float tile[NCH][31];

    for (int idx = threadIdx.x; idx < NCH * 30; idx += blockDim.x) {
        int c = idx / 30, w = idx % 30;
        tile[c][w] = plane[(((size_t)i * NCH + c) * RES + h) * RES + w0 + w];
    }
    __syncthreads();
    float* dst = g_plane_t + (((size_t)i * RES + h) * RES + w0) * NCH;
    for (int idx = threadIdx.x; idx < NCH * 30; idx += blockDim.x) {
        int w = idx / NCH, c = idx % NCH;
        dst[(size_t)w * NCH + c] = tile[c][w];
    }
}

// ---------------------------------------------------------------------------
// Fused kernel, WARP-AUTONOMOUS mode pipeline (no block barriers after init):
//   each warp owns 32 samples + a private F slab (32 x 68 floats)
//   for i in 0..2:  gather_i -> syncwarp -> project_i -> syncwarp
// smem (floats): xyz[384] | W[144][28] | slabs[4][32*68]  (52.5 KB, 4 blk/SM)
// ---------------------------------------------------------------------------
#define XYZ_OFF 0
#define W_OFF   (3 * SPB)                       // 384
#define F_OFF   (W_OFF + 144 * 28)              // 4416
#define SLAB    (32 * 68)                       // floats per warp slab
#define F_ROW2  17                              // 68 floats = 17 x 16B
#define SMEM_FLOATS (F_OFF + 4 * SLAB)          // 13120 -> 52480 bytes

__global__ void __launch_bounds__(BLOCK, 4)
fused_kernel(const float* __restrict__ xyz,
             const float* __restrict__ basisW,   // (27, 144) row-major
             float* __restrict__ out, int N)
{
    extern __shared__ __align__(16) float sm[];
    float* xyzsm = sm + XYZ_OFF;
    float* Wsm   = sm + W_OFF;

    const int tid = threadIdx.x;
    const long base = (long)blockIdx.x * SPB;

    // ---- phase 0: stage xyz + W (broadcast layout, zero pad col) ----
    for (int idx = tid; idx < 3 * SPB; idx += BLOCK) {
        long g = base * 3 + idx;
        xyzsm[idx] = (g < (long)3 * N) ? xyz[g] : 0.f;
    }
    for (int idx = tid; idx < APP_DIM * 144; idx += BLOCK) {
        int d = idx / 144, j = idx - d * 144;
        Wsm[j * 28 + d] = basisW[idx];           // coalesced global read
    }
    if (tid < 144) Wsm[tid * 28 + 27] = 0.f;
    __syncthreads();                              // the ONLY block barrier

    const ulonglong2* GP = (const ulonglong2*)g_plane_t;
    const ulonglong2* GL = (const ulonglong2*)g_line_t;
    const int lane = tid & 31;
    const int c4   = lane & 15;         // channel quad within 16-lane group
    const int half = lane >> 4;         // which sample of the pair
    const int wrp  = tid >> 5;          // 0..3

    ulonglong2* F2 = (ulonglong2*)(sm + F_OFF + wrp * SLAB);  // warp slab
    const float* xyzw = xyzsm + wrp * 32 * 3;                 // warp's xyz

    u64 acc2[14];
#pragma unroll
    for (int k = 0; k < 14; k++) acc2[k] = 0ULL;
    u64 sig2 = 0ULL;

#pragma unroll
    for (int i = 0; i < 3; i++) {
        // ---- gather_i: 16-lane group per sample, into warp slab ----
#pragma unroll 2
        for (int k = 0; k < 16; k++) {
            int sl = k * 2 + half;               // slab row 0..31
            float cx = xyzw[sl * 3 + 0];
            float cy = xyzw[sl * 3 + 1];
            float cz = xyzw[sl * 3 + 2];
            // MAT_MODE = {0,1},{0,2},{1,2}; VEC_MODE = {2,1,0}
            float gx = (i == 2) ? cy : cx;
            float gy = (i == 0) ? cy : cz;
            float gz = (i == 0) ? cz : ((i == 1) ? cy : cx);

            float ix = (gx + 1.f) * 0.5f * (float)(RES - 1);
            float iy = (gy + 1.f) * 0.5f * (float)(RES - 1);
            float iz = (gz + 1.f) * 0.5f * (float)(RES - 1);
            float x0f = floorf(ix), y0f = floorf(iy), z0f = floorf(iz);
            int x0 = (int)x0f, y0 = (int)y0f, z0 = (int)z0f;
            float wx = ix - x0f, wy = iy - y0f, wz = iz - z0f;
            int y1 = y0 + 1;
            if (y1 > RES - 1) { y1 = RES - 1; wy = 0.f; }
            // x/z +1 may read one quad past the row (pad): weight 0
            if (x0 + 1 > RES - 1) wx = 0.f;
            if (z0 + 1 > RES - 1) wz = 0.f;

            int r0 = (i * RES + y0) * RES + x0;
            int r1 = (i * RES + y1) * RES + x0;
            int rl =  i * RES + z0;
            ulonglong2 a00 = GP[r0 * 16 + c4];
            ulonglong2 a01 = GP[(r0 + 1) * 16 + c4];
            ulonglong2 a10 = GP[r1 * 16 + c4];
            ulonglong2 a11 = GP[(r1 + 1) * 16 + c4];
            ulonglong2 l0  = GL[rl * 16 + c4];
            ulonglong2 l1  = GL[(rl + 1) * 16 + c4];

            u64 w00p = pack2((1.f - wx) * (1.f - wy));
            u64 w01p = pack2(wx * (1.f - wy));
            u64 w10p = pack2((1.f - wx) * wy);
            u64 w11p = pack2(wx * wy);
            u64 wl0p = pack2(1.f - wz);
            u64 wl1p = pack2(wz);

            ulonglong2 f;
            u64 t, u;
            t = fma2(w00p, a00.x, fma2(w01p, a01.x,
                 fma2(w10p, a10.x, mul2(w11p, a11.x))));
            u = fma2(wl0p, l0.x, mul2(wl1p, l1.x));
            f.x = mul2(t, u);
            t = fma2(w00p, a00.y, fma2(w01p, a01.y,
                 fma2(w10p, a10.y, mul2(w11p, a11.y))));
            u = fma2(wl0p, l0.y, mul2(wl1p, l1.y));
            f.y = mul2(t, u);

            F2[sl * F_ROW2 + c4] = f;
        }
        __syncwarp();

        // ---- project_i: thread-per-sample from warp slab, W broadcast ----
        {
            const int fb = lane * F_ROW2;
            const float* wb = Wsm + i * NC_A * 28;

#pragma unroll 2
            for (int c4i = 0; c4i < NC_A / 4; c4i++) {
                float4 f = ((const float4*)F2)[fb + c4i];
                u64 fx = pack2(f.x), fy = pack2(f.y);
                u64 fz = pack2(f.z), fw = pack2(f.w);
                const ulonglong2* q0 = (const ulonglong2*)(wb + c4i * 4 * 28);
                const ulonglong2* q1 = (const ulonglong2*)(wb + c4i * 4 * 28 + 28);
                const ulonglong2* q2 = (const ulonglong2*)(wb + c4i * 4 * 28 + 56);
                const ulonglong2* q3 = (const ulonglong2*)(wb + c4i * 4 * 28 + 84);
#pragma unroll
                for (int p = 0; p < 7; p++) {
                    ulonglong2 v0 = q0[p], v1 = q1[p], v2 = q2[p], v3 = q3[p];
                    acc2[2*p]   = fma2(fx, v0.x, acc2[2*p]);
                    acc2[2*p+1] = fma2(fx, v0.y, acc2[2*p+1]);
                    acc2[2*p]   = fma2(fy, v1.x, acc2[2*p]);
                    acc2[2*p+1] = fma2(fy, v1.y, acc2[2*p+1]);
                    acc2[2*p]   = fma2(fz, v2.x, acc2[2*p]);
                    acc2[2*p+1] = fma2(fz, v2.y, acc2[2*p+1]);
                    acc2[2*p]   = fma2(fw, v3.x, acc2[2*p]);
                    acc2[2*p+1] = fma2(fw, v3.y, acc2[2*p+1]);
                }
            }
#pragma unroll
            for (int c4i = NC_A / 4; c4i < NCH / 4; c4i++) {
                ulonglong2 fd = F2[fb + c4i];
                sig2 = add2(sig2, add2(fd.x, fd.y));
            }
        }
        if (i < 2) __syncwarp();        // slab reused next mode
    }

    // ---- write out ----
    long n = base + wrp * 32 + lane;
    if (n < N) {
        out[n] = lo32(sig2) + hi32(sig2);
        float* ao = out + N + n * APP_DIM;
#pragma unroll
        for (int p = 0; p < 13; p++) {
            ao[2*p]   = lo32(acc2[p]);
            ao[2*p+1] = hi32(acc2[p]);
        }
        ao[26] = lo32(acc2[13]);
    }
}

extern "C" void kernel_launch(void* const* d_in, const int* in_sizes, int n_in,
                              void* d_out, int out_size) {
    const float* xyz   = (const float*)d_in[0];   // (N, 3)
    const float* plane = (const float*)d_in[1];   // (3, 64, 300, 300)
    const float* line  = (const float*)d_in[2];   // (3, 64, 300, 1)
    const float* W     = (const float*)d_in[3];   // (27, 144)
    float* out = (float*)d_out;
    int N = in_sizes[0] / 3;

    transpose_kernel<<<dim3(3 * RES, 11), 256>>>(plane, line);

    int smem_bytes = SMEM_FLOATS * (int)sizeof(float);   // 52480
    cudaFuncSetAttribute(fused_kernel,
                         cudaFuncAttributeMaxDynamicSharedMemorySize, smem_bytes);
    int grid = (N + SPB - 1) / SPB;
    fused_kernel<<<grid, BLOCK, smem_bytes>>>(xyz, W, out, N);
}